// round 3
// baseline (speedup 1.0000x reference)
#include <cuda_runtime.h>
#include <cstdint>

#define NN 100000
#define EE 6400000
#define PP 12
#define FF 32

// scratch (device globals: no allocations allowed)
__device__ __align__(16) float g_deg[NN];
__device__ __align__(16) float g_dinv[NN];
__device__ __align__(16) float g_agg[NN * PP];
__device__ float g_probs[PP];
__device__ float g_uz[FF], g_cz[FF], g_uh[FF], g_ch[FF];

__device__ __forceinline__ float tanh_fast(float x) {
    float r;
    asm("tanh.approx.f32 %0, %1;" : "=f"(r) : "f"(x));
    return r;
}

// ---- precompute: collapse GRU matmuls (H0==0) + softmax(attention) ----
__global__ void prep_kernel(const float* __restrict__ att,
                            const float* __restrict__ wcz, const float* __restrict__ bcz,
                            const float* __restrict__ wch, const float* __restrict__ bch,
                            const float* __restrict__ wlz, const float* __restrict__ blz,
                            const float* __restrict__ wlh, const float* __restrict__ blh) {
    int k = threadIdx.x;  // 32 threads
    float uz = 0.f, cz = blz[k], uh = 0.f, ch = blh[k];
#pragma unroll
    for (int j = 0; j < FF; j++) {
        float wz = wlz[j * FF + k], wh = wlh[j * FF + k];
        uz = fmaf(wcz[j], wz, uz);
        cz = fmaf(bcz[j], wz, cz);
        uh = fmaf(wch[j], wh, uh);
        ch = fmaf(bch[j], wh, ch);
    }
    g_uz[k] = uz; g_cz[k] = cz; g_uh[k] = uh; g_ch[k] = ch;
    if (k == 0) {
        float m = -1e30f;
        for (int p = 0; p < PP; p++) m = fmaxf(m, att[p]);
        float e[PP]; float s = 0.f;
        for (int p = 0; p < PP; p++) { e[p] = __expf(att[p] - m); s += e[p]; }
        float inv = 1.0f / s;
        for (int p = 0; p < PP; p++) g_probs[p] = e[p] * inv;
    }
}

// ---- zero deg + agg ----
__global__ void zero_kernel() {
    int i = blockIdx.x * blockDim.x + threadIdx.x;
    if (i < NN * PP) g_agg[i] = 0.f;
    if (i < NN) g_deg[i] = 0.f;
}

// ---- deg[dst] += w ----
__global__ void deg_kernel(const int* __restrict__ ei,
                           const float* __restrict__ ew) {
    int e = blockIdx.x * blockDim.x + threadIdx.x;
    if (e >= EE) return;
    int d = ei[EE + e];
    atomicAdd(&g_deg[d], ew[e]);
}

// ---- dinv = rsqrt(deg + 1) ----
__global__ void dinv_kernel() {
    int n = blockIdx.x * blockDim.x + threadIdx.x;
    if (n < NN) g_dinv[n] = rsqrtf(g_deg[n] + 1.0f);
}

// ---- agg[dst,:] += norm * x[src,:]  (12 scalar REDs per edge) ----
__global__ void agg_kernel(const int* __restrict__ ei,
                           const float* __restrict__ ew,
                           const float* __restrict__ x) {
    int e = blockIdx.x * blockDim.x + threadIdx.x;
    if (e >= EE) return;
    int s = ei[e];
    int d = ei[EE + e];
    float nw = g_dinv[s] * ew[e] * g_dinv[d];
    const float4* xs = (const float4*)(x + (size_t)s * PP);  // 48B rows -> 16B aligned
    float* dst = g_agg + (size_t)d * PP;
    float4 v0 = xs[0], v1 = xs[1], v2 = xs[2];
    atomicAdd(dst + 0,  nw * v0.x);
    atomicAdd(dst + 1,  nw * v0.y);
    atomicAdd(dst + 2,  nw * v0.z);
    atomicAdd(dst + 3,  nw * v0.w);
    atomicAdd(dst + 4,  nw * v1.x);
    atomicAdd(dst + 5,  nw * v1.y);
    atomicAdd(dst + 6,  nw * v1.z);
    atomicAdd(dst + 7,  nw * v1.w);
    atomicAdd(dst + 8,  nw * v2.x);
    atomicAdd(dst + 9,  nw * v2.y);
    atomicAdd(dst + 10, nw * v2.z);
    atomicAdd(dst + 11, nw * v2.w);
}

// ---- node pass: 1 warp per node; lane = feature k ----
__global__ void out_kernel(const float* __restrict__ x,
                           const float* __restrict__ w_out,
                           const float* __restrict__ b_out,
                           float* __restrict__ out) {
    int warp = (blockIdx.x * blockDim.x + threadIdx.x) >> 5;
    int lane = threadIdx.x & 31;
    if (warp >= NN) return;
    int n = warp;
    float dv = g_dinv[n];
    float sl = 0.f, pl = 0.f;
    if (lane < PP) {
        sl = g_agg[n * PP + lane] + dv * dv * x[n * PP + lane];
        pl = g_probs[lane];
    }
    float uz = g_uz[lane], cz = g_cz[lane], uh = g_uh[lane], ch = g_ch[lane];
    float acc = 0.f;
#pragma unroll
    for (int p = 0; p < PP; p++) {
        float s  = __shfl_sync(0xffffffffu, sl, p);
        float pr = __shfl_sync(0xffffffffu, pl, p);
        float a = fmaf(s, uz, cz);
        float b = fmaf(s, uh, ch);
        // (1 - sigmoid(a)) = 0.5*(1 - tanh(a/2))
        float t1 = tanh_fast(0.5f * a);
        float t2 = tanh_fast(b);
        acc = fmaf(pr, 0.5f * (1.0f - t1) * t2, acc);
    }
    float v = fmaxf(acc, 0.0f) * w_out[lane];
#pragma unroll
    for (int o = 16; o; o >>= 1) v += __shfl_xor_sync(0xffffffffu, v, o);
    if (lane == 0) out[n] = v + b_out[0];
}

extern "C" void kernel_launch(void* const* d_in, const int* in_sizes, int n_in,
                              void* d_out, int out_size) {
    const float* x   = (const float*)d_in[0];
    const int*   ei  = (const int*)d_in[1];   // JAX w/o x64: int64 silently -> int32
    const float* ew  = (const float*)d_in[2];
    const float* att = (const float*)d_in[3];
    const float* wcz = (const float*)d_in[4];
    const float* bcz = (const float*)d_in[5];
    // d_in[6], d_in[7] = wc_r, bc_r  (unused: H0 == 0 so R is irrelevant)
    const float* wch = (const float*)d_in[8];
    const float* bch = (const float*)d_in[9];
    const float* wlz = (const float*)d_in[10];
    const float* blz = (const float*)d_in[11];
    // d_in[12], d_in[13] = wl_r, bl_r (unused)
    const float* wlh = (const float*)d_in[14];
    const float* blh = (const float*)d_in[15];
    const float* wo  = (const float*)d_in[16];
    const float* bo  = (const float*)d_in[17];
    float*       out = (float*)d_out;

    prep_kernel<<<1, FF>>>(att, wcz, bcz, wch, bch, wlz, blz, wlh, blh);
    zero_kernel<<<(NN * PP + 255) / 256, 256>>>();
    deg_kernel<<<(EE + 255) / 256, 256>>>(ei, ew);
    dinv_kernel<<<(NN + 255) / 256, 256>>>();
    agg_kernel<<<(EE + 255) / 256, 256>>>(ei, ew, x);
    out_kernel<<<(NN * 32 + 255) / 256, 256>>>(x, wo, bo, out);
}

// round 4
// speedup vs baseline: 2.0018x; 2.0018x over previous
#include <cuda_runtime.h>
#include <cstdint>

#define NN 100000
#define EE 6400000
#define PP 12
#define FF 32

// scratch (device globals: no allocations allowed)
__device__ __align__(16) float g_deg[NN];
__device__ __align__(16) float g_dinv[NN];
__device__ __align__(16) float g_agg[NN * PP];
__device__ float g_probs[PP];
__device__ float g_uz[FF], g_cz[FF], g_uh[FF], g_ch[FF];

__device__ __forceinline__ float tanh_fast(float x) {
    float r;
    asm("tanh.approx.f32 %0, %1;" : "=f"(r) : "f"(x));
    return r;
}

// 16B-aligned vector reduction: 1 LSU issue for 4 float adds
__device__ __forceinline__ void red4(float* p, float a, float b, float c, float d) {
    asm volatile("red.global.add.v4.f32 [%0], {%1,%2,%3,%4};"
                 :: "l"(p), "f"(a), "f"(b), "f"(c), "f"(d) : "memory");
}

// ---- precompute: collapse GRU matmuls (H0==0) + softmax(attention) ----
__global__ void prep_kernel(const float* __restrict__ att,
                            const float* __restrict__ wcz, const float* __restrict__ bcz,
                            const float* __restrict__ wch, const float* __restrict__ bch,
                            const float* __restrict__ wlz, const float* __restrict__ blz,
                            const float* __restrict__ wlh, const float* __restrict__ blh) {
    int k = threadIdx.x;  // 32 threads
    float uz = 0.f, cz = blz[k], uh = 0.f, ch = blh[k];
#pragma unroll
    for (int j = 0; j < FF; j++) {
        float wz = wlz[j * FF + k], wh = wlh[j * FF + k];
        uz = fmaf(wcz[j], wz, uz);
        cz = fmaf(bcz[j], wz, cz);
        uh = fmaf(wch[j], wh, uh);
        ch = fmaf(bch[j], wh, ch);
    }
    g_uz[k] = uz; g_cz[k] = cz; g_uh[k] = uh; g_ch[k] = ch;
    if (k == 0) {
        float m = -1e30f;
        for (int p = 0; p < PP; p++) m = fmaxf(m, att[p]);
        float e[PP]; float s = 0.f;
        for (int p = 0; p < PP; p++) { e[p] = __expf(att[p] - m); s += e[p]; }
        float inv = 1.0f / s;
        for (int p = 0; p < PP; p++) g_probs[p] = e[p] * inv;
    }
}

// ---- zero deg + agg ----
__global__ void zero_kernel() {
    int i = blockIdx.x * blockDim.x + threadIdx.x;
    if (i < NN * PP) g_agg[i] = 0.f;
    if (i < NN) g_deg[i] = 0.f;
}

// ---- deg[dst] += w ----
__global__ void deg_kernel(const int* __restrict__ ei,
                           const float* __restrict__ ew) {
    int e = blockIdx.x * blockDim.x + threadIdx.x;
    if (e >= EE) return;
    int d = ei[EE + e];
    atomicAdd(&g_deg[d], ew[e]);
}

// ---- dinv = rsqrt(deg + 1) ----
__global__ void dinv_kernel() {
    int n = blockIdx.x * blockDim.x + threadIdx.x;
    if (n < NN) g_dinv[n] = rsqrtf(g_deg[n] + 1.0f);
}

// ---- agg[dst,:] += norm * x[src,:]  (3 x v4 vector RED per edge) ----
__global__ void agg_kernel(const int* __restrict__ ei,
                           const float* __restrict__ ew,
                           const float* __restrict__ x) {
    int e = blockIdx.x * blockDim.x + threadIdx.x;
    if (e >= EE) return;
    int s = ei[e];
    int d = ei[EE + e];
    float nw = g_dinv[s] * ew[e] * g_dinv[d];
    const float4* xs = (const float4*)(x + (size_t)s * PP);  // 48B rows -> 16B aligned
    float* dst = g_agg + (size_t)d * PP;                     // 48B rows -> 16B aligned
    float4 v0 = xs[0], v1 = xs[1], v2 = xs[2];
    red4(dst + 0, nw * v0.x, nw * v0.y, nw * v0.z, nw * v0.w);
    red4(dst + 4, nw * v1.x, nw * v1.y, nw * v1.z, nw * v1.w);
    red4(dst + 8, nw * v2.x, nw * v2.y, nw * v2.z, nw * v2.w);
}

// ---- node pass: 1 warp per node; lane = feature k ----
__global__ void out_kernel(const float* __restrict__ x,
                           const float* __restrict__ w_out,
                           const float* __restrict__ b_out,
                           float* __restrict__ out) {
    int warp = (blockIdx.x * blockDim.x + threadIdx.x) >> 5;
    int lane = threadIdx.x & 31;
    if (warp >= NN) return;
    int n = warp;
    float dv = g_dinv[n];
    float sl = 0.f, pl = 0.f;
    if (lane < PP) {
        sl = g_agg[n * PP + lane] + dv * dv * x[n * PP + lane];
        pl = g_probs[lane];
    }
    float uz = g_uz[lane], cz = g_cz[lane], uh = g_uh[lane], ch = g_ch[lane];
    float acc = 0.f;
#pragma unroll
    for (int p = 0; p < PP; p++) {
        float s  = __shfl_sync(0xffffffffu, sl, p);
        float pr = __shfl_sync(0xffffffffu, pl, p);
        float a = fmaf(s, uz, cz);
        float b = fmaf(s, uh, ch);
        // (1 - sigmoid(a)) = 0.5*(1 - tanh(a/2))
        float t1 = tanh_fast(0.5f * a);
        float t2 = tanh_fast(b);
        acc = fmaf(pr, 0.5f * (1.0f - t1) * t2, acc);
    }
    float v = fmaxf(acc, 0.0f) * w_out[lane];
#pragma unroll
    for (int o = 16; o; o >>= 1) v += __shfl_xor_sync(0xffffffffu, v, o);
    if (lane == 0) out[n] = v + b_out[0];
}

extern "C" void kernel_launch(void* const* d_in, const int* in_sizes, int n_in,
                              void* d_out, int out_size) {
    const float* x   = (const float*)d_in[0];
    const int*   ei  = (const int*)d_in[1];   // JAX w/o x64: int64 silently -> int32
    const float* ew  = (const float*)d_in[2];
    const float* att = (const float*)d_in[3];
    const float* wcz = (const float*)d_in[4];
    const float* bcz = (const float*)d_in[5];
    // d_in[6], d_in[7] = wc_r, bc_r  (unused: H0 == 0 so R is irrelevant)
    const float* wch = (const float*)d_in[8];
    const float* bch = (const float*)d_in[9];
    const float* wlz = (const float*)d_in[10];
    const float* blz = (const float*)d_in[11];
    // d_in[12], d_in[13] = wl_r, bl_r (unused)
    const float* wlh = (const float*)d_in[14];
    const float* blh = (const float*)d_in[15];
    const float* wo  = (const float*)d_in[16];
    const float* bo  = (const float*)d_in[17];
    float*       out = (float*)d_out;

    prep_kernel<<<1, FF>>>(att, wcz, bcz, wch, bch, wlz, blz, wlh, blh);
    zero_kernel<<<(NN * PP + 255) / 256, 256>>>();
    deg_kernel<<<(EE + 255) / 256, 256>>>(ei, ew);
    dinv_kernel<<<(NN + 255) / 256, 256>>>();
    agg_kernel<<<(EE + 255) / 256, 256>>>(ei, ew, x);
    out_kernel<<<(NN * 32 + 255) / 256, 256>>>(x, wo, bo, out);
}